// round 5
// baseline (speedup 1.0000x reference)
#include <cuda_runtime.h>

#define VV   128
#define HH   512
#define BB   8192
#define OUTW 256   // 2*V

#define VG   8            // v's per phase-A block
#define KT   32           // k's per phase-A block
#define KS2  (HH / KT)    // 16 k-segments
#define VGN2 (VV / VG)    // 16 v-groups
#define NBLK 256
#define THR  512

// Scratch (alloc-free rule: __device__ globals).
__device__ float    g_part[KS2 * VV * OUTW];   // 2 MB partial sums
__device__ int      g_loc[VV];
__device__ int      g_scale[VV];
__device__ unsigned g_bar1 = 0u;               // monotonic tickets, never reset
__device__ unsigned g_bar2 = 0u;

// Monotonic grid barrier: ticket/epoch scheme survives graph replays without
// resets. All NBLK blocks are guaranteed co-resident (256 <= 148*2).
__device__ __forceinline__ void grid_barrier(unsigned* ctr)
{
    __syncthreads();                       // block's prior work done
    if (threadIdx.x == 0) {
        __threadfence();                   // release our global writes
        const unsigned ticket = atomicAdd(ctr, 1u);
        const unsigned target = (ticket / NBLK + 1u) * NBLK;
        while ((int)(*(volatile unsigned*)ctr - target) < 0)
            __nanosleep(32);
        __threadfence();                   // acquire others' writes
    }
    __syncthreads();
}

__global__ void __launch_bounds__(THR, 2)
fused_kernel(const float* __restrict__ in, const float* __restrict__ W1,
             const float* __restrict__ b1, const float* __restrict__ W2,
             const float* __restrict__ b2, float* __restrict__ out)
{
    const int blk = blockIdx.x;
    const int t = threadIdx.x;
    const int wid = t >> 5, lane = t & 31;

    __shared__ __align__(16) float h[KT][VG];        // 1 KB
    __shared__ __align__(16) float red[8][32][36];   // 36 KB (reused in B)
    __shared__ unsigned long long skey;

    // ===================== Phase A: partial GEMM ============================
    // Block (vg, ks): 8 v's x 32 k's x 256 cols. Warp = (k-quad kq, c-half ch).
    {
        const int vg = blk & (VGN2 - 1);
        const int ks = blk >> 4;
        const int v0 = vg * VG;
        const int k0 = ks * KT;
        const int kq = wid & 7;
        const int ch = wid >> 3;

        if (t < KT * VG) {
            const int k = t >> 3, v = t & 7;
            h[k][v] = fmaxf(W1[(size_t)(v0 + v) * HH + k0 + k] + b1[k0 + k], 0.0f);
        }
        __syncthreads();

        float4 acc[VG];
        #pragma unroll
        for (int v = 0; v < VG; ++v) acc[v] = make_float4(0.f, 0.f, 0.f, 0.f);

        const float4* w2p = reinterpret_cast<const float4*>(
            W2 + (size_t)(k0 + kq * 4) * OUTW) + ch * 32 + lane;

        #pragma unroll
        for (int j = 0; j < 4; ++j) {
            const float4 w = w2p[(size_t)j * (OUTW / 4)];
            const float* hrow = h[kq * 4 + j];       // broadcast LDS
            #pragma unroll
            for (int v = 0; v < VG; ++v) {
                const float s = hrow[v];
                acc[v].x = fmaf(s, w.x, acc[v].x);
                acc[v].y = fmaf(s, w.y, acc[v].y);
                acc[v].z = fmaf(s, w.z, acc[v].z);
                acc[v].w = fmaf(s, w.w, acc[v].w);
            }
        }

        // Cross-kq reduce, one c-half at a time.
        #pragma unroll
        for (int p = 0; p < 2; ++p) {
            if (ch == p) {
                #pragma unroll
                for (int v = 0; v < VG; ++v)
                    *reinterpret_cast<float4*>(&red[kq][lane][v * 4]) = acc[v];
            }
            __syncthreads();
            #pragma unroll
            for (int rep = 0; rep < 2; ++rep) {
                const int o = t + rep * THR;        // 0..1023 = 8v x 128c
                const int v = o >> 7, cl = o & 127;
                float s = 0.0f;
                #pragma unroll
                for (int q = 0; q < 8; ++q)
                    s += red[q][cl >> 2][v * 4 + (cl & 3)];
                g_part[((size_t)ks * VV + v0 + v) * OUTW + p * 128 + cl] = s;
            }
            __syncthreads();
        }
    }

    grid_barrier(&g_bar1);

    // ===================== Phase B: reduce + argmax =========================
    // Block (v, half): sum 16 k-segment partials + b2 over 128 cols, argmax
    // with first-index tie-break, write g_loc / g_scale.
    {
        const int v = blk >> 1;
        const int half = blk & 1;
        const int c = t & 127;
        const int q = t >> 7;                       // 0..3 -> 4 ksegs each
        float* st = &red[0][0][0];                  // reuse smem: 512 floats

        float s = 0.0f;
        #pragma unroll
        for (int j = 0; j < 4; ++j)
            s += g_part[((size_t)(q * 4 + j) * VV + v) * OUTW + half * 128 + c];
        st[q * 128 + c] = s;
        if (t == 0) skey = 0ULL;
        __syncthreads();

        if (t < 128) {
            const float tot = st[t] + st[128 + t] + st[256 + t] + st[384 + t]
                              + b2[half * 128 + t];
            unsigned int u = __float_as_uint(tot);
            u = (u & 0x80000000u) ? ~u : (u | 0x80000000u);
            atomicMax(&skey, ((unsigned long long)u << 32)
                             | (unsigned long long)(127 - t));
        }
        __syncthreads();
        if (t == 0) {
            const int idx = 127 - (int)(skey & 0xFFFFFFFFULL);
            (half ? g_scale : g_loc)[v] = idx;
        }
    }

    grid_barrier(&g_bar2);

    // ===================== Phase C: rows ====================================
    // 16 warps x 2 rows = 32 rows per block. x0/x1 are EXACT one-hots ->
    // ballot + ffs argmax. Emit [x0, onehot((L + i1*S) % 128)] (zero if S==0).
    {
        const int r0 = blk * 32 + wid * 2;
        const float4* in4 = reinterpret_cast<const float4*>(in);
        float4* out4 = reinterpret_cast<float4*>(out);

        float4 a[2], c[2];
        #pragma unroll
        for (int i = 0; i < 2; ++i) {
            const size_t base = (size_t)(r0 + i) * 64;
            a[i] = in4[base + lane];
            c[i] = in4[base + 32 + lane];
        }

        #pragma unroll
        for (int i = 0; i < 2; ++i) {
            const int m0 = (a[i].x == 1.0f) | ((a[i].y == 1.0f) << 1) |
                           ((a[i].z == 1.0f) << 2) | ((a[i].w == 1.0f) << 3);
            const int m1 = (c[i].x == 1.0f) | ((c[i].y == 1.0f) << 1) |
                           ((c[i].z == 1.0f) << 2) | ((c[i].w == 1.0f) << 3);

            const unsigned bal0 = __ballot_sync(0xFFFFFFFFu, m0 != 0);
            const unsigned bal1 = __ballot_sync(0xFFFFFFFFu, m1 != 0);
            const int ln0 = __ffs(bal0) - 1;
            const int ln1 = __ffs(bal1) - 1;
            const int i0 = ln0 * 4 + __ffs(__shfl_sync(0xFFFFFFFFu, m0, ln0)) - 1;
            const int i1 = ln1 * 4 + __ffs(__shfl_sync(0xFFFFFFFFu, m1, ln1)) - 1;

            const int l = g_loc[i0];
            const int s = g_scale[i0];

            const size_t base = (size_t)(r0 + i) * 64;
            out4[base + lane] = a[i];

            float4 z = make_float4(0.f, 0.f, 0.f, 0.f);
            if (s != 0) {
                const int tcol = (l + i1 * s) & (VV - 1);
                if ((tcol >> 2) == lane)
                    reinterpret_cast<float*>(&z)[tcol & 3] = 1.0f;
            }
            out4[base + 32 + lane] = z;
        }
    }
}

// ---------------------------------------------------------------------------
// Launch: inputs in setup_inputs() order: inputs, W1, b1, W2, b2.
// ---------------------------------------------------------------------------
extern "C" void kernel_launch(void* const* d_in, const int* in_sizes, int n_in,
                              void* d_out, int out_size)
{
    const float* in = (const float*)d_in[0];
    const float* W1 = (const float*)d_in[1];
    const float* b1 = (const float*)d_in[2];
    const float* W2 = (const float*)d_in[3];
    const float* b2 = (const float*)d_in[4];
    float* out = (float*)d_out;

    fused_kernel<<<NBLK, THR>>>(in, W1, b1, W2, b2, out);
}

// round 6
// speedup vs baseline: 1.0129x; 1.0129x over previous
#include <cuda_runtime.h>

#define VV   128
#define HH   512
#define BB   8192
#define OUTW 256   // 2*V

#define VG   8            // v's per phase-A block
#define KT   32           // k's per phase-A block
#define KS2  (HH / KT)    // 16 k-segments
#define VGN2 (VV / VG)    // 16 v-groups
#define NBLK 256
#define THR  512

// Scratch (alloc-free rule: __device__ globals).
__device__ float    g_part[KS2 * VV * OUTW];   // 2 MB partial sums
__device__ int      g_loc[VV];
__device__ int      g_scale[VV];
__device__ unsigned g_bar1 = 0u;               // monotonic tickets, never reset
__device__ unsigned g_bar2 = 0u;

// Monotonic grid barrier: ticket/epoch scheme survives graph replays without
// resets. All NBLK blocks are guaranteed co-resident (256 <= 148*2).
__device__ __forceinline__ void grid_barrier(unsigned* ctr)
{
    __syncthreads();                       // block's prior work done
    if (threadIdx.x == 0) {
        __threadfence();                   // release our global writes
        const unsigned ticket = atomicAdd(ctr, 1u);
        const unsigned target = (ticket / NBLK + 1u) * NBLK;
        while ((int)(*(volatile unsigned*)ctr - target) < 0)
            __nanosleep(32);
        __threadfence();                   // acquire others' writes
    }
    __syncthreads();
}

__global__ void __launch_bounds__(THR, 2)
fused_kernel(const float* __restrict__ in, const float* __restrict__ W1,
             const float* __restrict__ b1, const float* __restrict__ W2,
             const float* __restrict__ b2, float* __restrict__ out)
{
    const int blk = blockIdx.x;
    const int t = threadIdx.x;
    const int wid = t >> 5, lane = t & 31;

    __shared__ __align__(16) float h[KT][VG];        // 1 KB
    __shared__ __align__(16) float red[8][32][36];   // 36 KB (reused in B)
    __shared__ unsigned long long skey;

    // ===================== Phase A: partial GEMM ============================
    // Block (vg, ks): 8 v's x 32 k's x 256 cols. Warp = (k-quad kq, c-half ch).
    // Rolling prefetch of W2 keeps the live set ~50 regs -> no spills.
    {
        const int vg = blk & (VGN2 - 1);
        const int ks = blk >> 4;
        const int v0 = vg * VG;
        const int k0 = ks * KT;
        const int kq = wid & 7;
        const int ch = wid >> 3;

        if (t < KT * VG) {
            const int k = t >> 3, v = t & 7;
            h[k][v] = fmaxf(W1[(size_t)(v0 + v) * HH + k0 + k] + b1[k0 + k], 0.0f);
        }
        __syncthreads();

        float4 acc[VG];
        #pragma unroll
        for (int v = 0; v < VG; ++v) acc[v] = make_float4(0.f, 0.f, 0.f, 0.f);

        const float4* w2p = reinterpret_cast<const float4*>(
            W2 + (size_t)(k0 + kq * 4) * OUTW) + ch * 32 + lane;

        float4 w = w2p[0];                            // prefetch j=0
        #pragma unroll
        for (int j = 0; j < 4; ++j) {
            const float4 wn = w2p[(size_t)((j < 3) ? (j + 1) : 0) * (OUTW / 4)];
            const float* hrow = h[kq * 4 + j];        // broadcast LDS
            #pragma unroll
            for (int v = 0; v < VG; ++v) {
                const float s = hrow[v];
                acc[v].x = fmaf(s, w.x, acc[v].x);
                acc[v].y = fmaf(s, w.y, acc[v].y);
                acc[v].z = fmaf(s, w.z, acc[v].z);
                acc[v].w = fmaf(s, w.w, acc[v].w);
            }
            w = wn;
        }

        // Cross-kq reduce, one c-half at a time (36 KB staging reused).
        #pragma unroll
        for (int p = 0; p < 2; ++p) {
            if (ch == p) {
                #pragma unroll
                for (int v = 0; v < VG; ++v)
                    *reinterpret_cast<float4*>(&red[kq][lane][v * 4]) = acc[v];
            }
            __syncthreads();
            #pragma unroll
            for (int rep = 0; rep < 2; ++rep) {
                const int o = t + rep * THR;        // 0..1023 = 8v x 128c
                const int v = o >> 7, cl = o & 127;
                float s = 0.0f;
                #pragma unroll
                for (int q = 0; q < 8; ++q)
                    s += red[q][cl >> 2][v * 4 + (cl & 3)];
                g_part[((size_t)ks * VV + v0 + v) * OUTW + p * 128 + cl] = s;
            }
            __syncthreads();
        }
    }

    grid_barrier(&g_bar1);

    // ===================== Phase B: reduce + argmax =========================
    // Block (v, half): sum 16 k-segment partials + b2 over 128 cols, argmax
    // with first-index tie-break, write g_loc / g_scale.
    {
        const int v = blk >> 1;
        const int half = blk & 1;
        const int c = t & 127;
        const int q = t >> 7;                       // 0..3 -> 4 ksegs each
        float* st = &red[0][0][0];                  // reuse smem: 512 floats

        float s = 0.0f;
        #pragma unroll
        for (int j = 0; j < 4; ++j)
            s += g_part[((size_t)(q * 4 + j) * VV + v) * OUTW + half * 128 + c];
        st[q * 128 + c] = s;
        if (t == 0) skey = 0ULL;
        __syncthreads();

        if (t < 128) {
            const float tot = st[t] + st[128 + t] + st[256 + t] + st[384 + t]
                              + b2[half * 128 + t];
            unsigned int u = __float_as_uint(tot);
            u = (u & 0x80000000u) ? ~u : (u | 0x80000000u);
            atomicMax(&skey, ((unsigned long long)u << 32)
                             | (unsigned long long)(127 - t));
        }
        __syncthreads();
        if (t == 0) {
            const int idx = 127 - (int)(skey & 0xFFFFFFFFULL);
            (half ? g_scale : g_loc)[v] = idx;
        }
    }

    grid_barrier(&g_bar2);

    // ===================== Phase C: rows ====================================
    // 16 warps x 2 rows = 32 rows per block. x0/x1 are EXACT one-hots ->
    // ballot + ffs argmax. Emit [x0, onehot((L + i1*S) % 128)] (zero if S==0).
    {
        const int r0 = blk * 32 + wid * 2;
        const float4* in4 = reinterpret_cast<const float4*>(in);
        float4* out4 = reinterpret_cast<float4*>(out);

        float4 a[2], c[2];
        #pragma unroll
        for (int i = 0; i < 2; ++i) {
            const size_t base = (size_t)(r0 + i) * 64;
            a[i] = in4[base + lane];
            c[i] = in4[base + 32 + lane];
        }

        #pragma unroll
        for (int i = 0; i < 2; ++i) {
            const int m0 = (a[i].x == 1.0f) | ((a[i].y == 1.0f) << 1) |
                           ((a[i].z == 1.0f) << 2) | ((a[i].w == 1.0f) << 3);
            const int m1 = (c[i].x == 1.0f) | ((c[i].y == 1.0f) << 1) |
                           ((c[i].z == 1.0f) << 2) | ((c[i].w == 1.0f) << 3);

            const unsigned bal0 = __ballot_sync(0xFFFFFFFFu, m0 != 0);
            const unsigned bal1 = __ballot_sync(0xFFFFFFFFu, m1 != 0);
            const int ln0 = __ffs(bal0) - 1;
            const int ln1 = __ffs(bal1) - 1;
            const int i0 = ln0 * 4 + __ffs(__shfl_sync(0xFFFFFFFFu, m0, ln0)) - 1;
            const int i1 = ln1 * 4 + __ffs(__shfl_sync(0xFFFFFFFFu, m1, ln1)) - 1;

            const int l = g_loc[i0];
            const int s = g_scale[i0];

            const size_t base = (size_t)(r0 + i) * 64;
            out4[base + lane] = a[i];

            float4 z = make_float4(0.f, 0.f, 0.f, 0.f);
            if (s != 0) {
                const int tcol = (l + i1 * s) & (VV - 1);
                if ((tcol >> 2) == lane)
                    reinterpret_cast<float*>(&z)[tcol & 3] = 1.0f;
            }
            out4[base + 32 + lane] = z;
        }
    }
}

// ---------------------------------------------------------------------------
// Launch: inputs in setup_inputs() order: inputs, W1, b1, W2, b2.
// ---------------------------------------------------------------------------
extern "C" void kernel_launch(void* const* d_in, const int* in_sizes, int n_in,
                              void* d_out, int out_size)
{
    const float* in = (const float*)d_in[0];
    const float* W1 = (const float*)d_in[1];
    const float* b1 = (const float*)d_in[2];
    const float* W2 = (const float*)d_in[3];
    const float* b2 = (const float*)d_in[4];
    float* out = (float*)d_out;

    fused_kernel<<<NBLK, THR>>>(in, W1, b1, W2, b2, out);
}

// round 7
// speedup vs baseline: 1.1779x; 1.1629x over previous
#include <cuda_runtime.h>

#define VV   128
#define HH   512
#define BB   8192
#define OUTW 256   // 2*V

#define VG   8            // v's per GEMM block
#define KT   64           // k's per GEMM block
#define KS2  (HH / KT)    // 8 k-segments
#define VGN2 (VV / VG)    // 16 v-groups
#define NBLK 256
#define THR  512

// Scratch (alloc-free rule: __device__ globals).
__device__ float    g_part[KS2 * VV * OUTW];   // 1 MB partial sums
__device__ int      g_loc[VV];
__device__ int      g_scale[VV];
__device__ int      g_idx[BB];                 // packed (i0 | i1<<8) per row
__device__ unsigned g_bar1 = 0u;               // monotonic tickets, never reset
__device__ unsigned g_bar2 = 0u;

// Monotonic grid barrier (graph-replay safe; 256 blocks all co-resident).
__device__ __forceinline__ void grid_barrier(unsigned* ctr)
{
    __syncthreads();
    if (threadIdx.x == 0) {
        __threadfence();
        const unsigned ticket = atomicAdd(ctr, 1u);
        const unsigned target = (ticket / NBLK + 1u) * NBLK;
        while ((int)(*(volatile unsigned*)ctr - target) < 0)
            __nanosleep(32);
        __threadfence();
    }
    __syncthreads();
}

__global__ void __launch_bounds__(THR, 2)
fused_kernel(const float* __restrict__ in, const float* __restrict__ W1,
             const float* __restrict__ b1, const float* __restrict__ W2,
             const float* __restrict__ b2, float* __restrict__ out)
{
    const int blk = blockIdx.x;
    const int t = threadIdx.x;
    const int wid = t >> 5, lane = t & 31;

    __shared__ __align__(16) float h[KT][VG];        // 2 KB
    __shared__ __align__(16) float red[8][32][36];   // 36 KB (reused in B)
    __shared__ unsigned long long skey;

    if (blk < 128) {
        // ================= GEMM duty: partial net over a k-segment ==========
        // Block (vg, ks): 8 v's x 64 k's x 256 cols. Warp = (kq 0..7, ch 0..1),
        // kq covers 8 k's. Per thread: 8 LDG.128 + 16 LDS.128 + 256 FFMA.
        const int vg = blk & (VGN2 - 1);   // 0..15
        const int ks = blk >> 4;           // 0..7
        const int v0 = vg * VG;
        const int k0 = ks * KT;
        const int kq = wid & 7;
        const int ch = wid >> 3;

        {
            const int k = t >> 3, v = t & 7;   // 512 threads fill 64x8
            h[k][v] = fmaxf(W1[(size_t)(v0 + v) * HH + k0 + k] + b1[k0 + k], 0.0f);
        }
        __syncthreads();

        float4 acc[VG];
        #pragma unroll
        for (int v = 0; v < VG; ++v) acc[v] = make_float4(0.f, 0.f, 0.f, 0.f);

        const float4* w2p = reinterpret_cast<const float4*>(
            W2 + (size_t)(k0 + kq * 8) * OUTW) + ch * 32 + lane;

        #pragma unroll
        for (int j = 0; j < 8; ++j) {
            const float4 w = w2p[(size_t)j * (OUTW / 4)];
            const float* hrow = h[kq * 8 + j];       // broadcast LDS
            #pragma unroll
            for (int v = 0; v < VG; ++v) {
                const float s = hrow[v];
                acc[v].x = fmaf(s, w.x, acc[v].x);
                acc[v].y = fmaf(s, w.y, acc[v].y);
                acc[v].z = fmaf(s, w.z, acc[v].z);
                acc[v].w = fmaf(s, w.w, acc[v].w);
            }
        }

        // Cross-kq reduce, one c-half at a time (36 KB staging).
        #pragma unroll
        for (int p = 0; p < 2; ++p) {
            if (ch == p) {
                #pragma unroll
                for (int v = 0; v < VG; ++v)
                    *reinterpret_cast<float4*>(&red[kq][lane][v * 4]) = acc[v];
            }
            __syncthreads();
            #pragma unroll
            for (int rep = 0; rep < 2; ++rep) {
                const int o = t + rep * THR;        // 0..1023 = 8v x 128c
                const int v = o >> 7, cl = o & 127;
                float s = 0.0f;
                #pragma unroll
                for (int q = 0; q < 8; ++q)
                    s += red[q][cl >> 2][v * 4 + (cl & 3)];
                g_part[((size_t)ks * VV + v0 + v) * OUTW + p * 128 + cl] = s;
            }
            __syncthreads();
        }
    } else {
        // ================= Copy duty: 64 rows, no table dependency ==========
        // Copy x0 -> out[:128], zero out[128:], extract (i0,i1) -> g_idx.
        const int rb = blk - 128;
        const int r0 = rb * 64 + wid * 4;   // 16 warps x 4 rows
        const float4* in4 = reinterpret_cast<const float4*>(in);
        float4* out4 = reinterpret_cast<float4*>(out);

        float4 a[4], c[4];
        #pragma unroll
        for (int i = 0; i < 4; ++i) {       // front-batched: MLP 8
            const size_t base = (size_t)(r0 + i) * 64;
            a[i] = in4[base + lane];
            c[i] = in4[base + 32 + lane];
        }

        const float4 z4 = make_float4(0.f, 0.f, 0.f, 0.f);
        #pragma unroll
        for (int i = 0; i < 4; ++i) {
            const int m0 = (a[i].x == 1.0f) | ((a[i].y == 1.0f) << 1) |
                           ((a[i].z == 1.0f) << 2) | ((a[i].w == 1.0f) << 3);
            const int m1 = (c[i].x == 1.0f) | ((c[i].y == 1.0f) << 1) |
                           ((c[i].z == 1.0f) << 2) | ((c[i].w == 1.0f) << 3);
            const unsigned bal0 = __ballot_sync(0xFFFFFFFFu, m0 != 0);
            const unsigned bal1 = __ballot_sync(0xFFFFFFFFu, m1 != 0);
            const int ln0 = __ffs(bal0) - 1;
            const int ln1 = __ffs(bal1) - 1;
            const int i0 = ln0 * 4 + __ffs(__shfl_sync(0xFFFFFFFFu, m0, ln0)) - 1;
            const int i1 = ln1 * 4 + __ffs(__shfl_sync(0xFFFFFFFFu, m1, ln1)) - 1;

            const size_t base = (size_t)(r0 + i) * 64;
            out4[base + lane] = a[i];
            out4[base + 32 + lane] = z4;
            if (lane == 0) g_idx[r0 + i] = i0 | (i1 << 8);
        }
    }

    grid_barrier(&g_bar1);

    // ===================== Phase B: reduce + argmax =========================
    // Block (v, half): sum 8 k-segment partials + b2 over 128 cols, argmax
    // with first-index tie-break, write g_loc / g_scale.
    {
        const int v = blk >> 1;
        const int half = blk & 1;
        const int c = t & 127;
        const int q = t >> 7;                       // 0..3 -> 2 ksegs each
        float* st = &red[0][0][0];                  // reuse smem: 512 floats

        float s = 0.0f;
        #pragma unroll
        for (int j = 0; j < 2; ++j)
            s += g_part[((size_t)(q * 2 + j) * VV + v) * OUTW + half * 128 + c];
        st[q * 128 + c] = s;
        if (t == 0) skey = 0ULL;
        __syncthreads();

        if (t < 128) {
            const float tot = st[t] + st[128 + t] + st[256 + t] + st[384 + t]
                              + b2[half * 128 + t];
            unsigned int u = __float_as_uint(tot);
            u = (u & 0x80000000u) ? ~u : (u | 0x80000000u);
            atomicMax(&skey, ((unsigned long long)u << 32)
                             | (unsigned long long)(127 - t));
        }
        __syncthreads();
        if (t == 0) {
            const int idx = 127 - (int)(skey & 0xFFFFFFFFULL);
            (half ? g_scale : g_loc)[v] = idx;
        }
    }

    grid_barrier(&g_bar2);

    // ===================== Phase C2: one-hot scatter ========================
    // Warp 0 of each block: 32 rows, one lane per row. Single conditional
    // 4-byte store into the already-zeroed second half.
    if (wid == 0) {
        const int row = blk * 32 + lane;
        const int packed = g_idx[row];
        const int i0 = packed & 255;
        const int i1 = packed >> 8;
        const int l = g_loc[i0];
        const int s = g_scale[i0];
        if (s != 0) {
            const int tcol = (l + i1 * s) & (VV - 1);
            out[(size_t)row * OUTW + VV + tcol] = 1.0f;
        }
    }
}

// ---------------------------------------------------------------------------
// Launch: inputs in setup_inputs() order: inputs, W1, b1, W2, b2.
// ---------------------------------------------------------------------------
extern "C" void kernel_launch(void* const* d_in, const int* in_sizes, int n_in,
                              void* d_out, int out_size)
{
    const float* in = (const float*)d_in[0];
    const float* W1 = (const float*)d_in[1];
    const float* b1 = (const float*)d_in[2];
    const float* W2 = (const float*)d_in[3];
    const float* b2 = (const float*)d_in[4];
    float* out = (float*)d_out;

    fused_kernel<<<NBLK, THR>>>(in, W1, b1, W2, b2, out);
}